// round 2
// baseline (speedup 1.0000x reference)
#include <cuda_runtime.h>
#include <cuda_fp16.h>
#include <cstdint>
#include <math.h>

// Problem constants
#define T_TOK 4096
#define D_MODEL 1024
#define D_MLP 3584
#define NEXP 8

// GEMM tile config
#define BM 64
#define BN 64
#define BK 32
#define PITCH 40   // halves per smem row (80B: 16B-aligned, conflict-free for frag loads)

// ---------------- device scratch (static: no cudaMalloc allowed) ----------------
static __device__ __half g_xh[T_TOK * D_MODEL];                 // x in fp16
static __device__ __half g_w1h[NEXP * D_MLP * D_MODEL];         // W1 fp16
static __device__ __half g_w3h[NEXP * D_MLP * D_MODEL];         // W3 fp16
static __device__ __half g_w2h[NEXP * D_MODEL * D_MLP];         // W2 fp16
static __device__ __half g_h[(size_t)NEXP * T_TOK * D_MLP];     // hidden activations per (expert, slot)
static __device__ int    g_cnt[NEXP];
static __device__ int    g_list[NEXP * T_TOK];
static __device__ float  g_wts[NEXP * T_TOK];

// ---------------- helpers ----------------
__device__ __forceinline__ void mma16816(float* c, const uint32_t* a, const uint32_t* b) {
    asm volatile(
        "mma.sync.aligned.m16n8k16.row.col.f32.f16.f16.f32 "
        "{%0,%1,%2,%3}, {%4,%5,%6,%7}, {%8,%9}, {%0,%1,%2,%3};"
        : "+f"(c[0]), "+f"(c[1]), "+f"(c[2]), "+f"(c[3])
        : "r"(a[0]), "r"(a[1]), "r"(a[2]), "r"(a[3]), "r"(b[0]), "r"(b[1]));
}

// ---------------- kernel 0: zero output + counters ----------------
__global__ void zero_kernel(float4* out4, int n4) {
    int i = blockIdx.x * blockDim.x + threadIdx.x;
    float4 z = make_float4(0.f, 0.f, 0.f, 0.f);
    for (; i < n4; i += gridDim.x * blockDim.x) out4[i] = z;
    if (blockIdx.x == 0 && threadIdx.x < NEXP) g_cnt[threadIdx.x] = 0;
}

// ---------------- kernel: fp32 -> fp16 conversion for the 3 weight tensors ----------------
// Destination is selected IN DEVICE CODE (device-global symbols must not be
// passed from host — host sees only the shadow symbol, which was the Round-1 bug).
__global__ void cvt_w_kernel(const float* __restrict__ w1,
                             const float* __restrict__ w3,
                             const float* __restrict__ w2) {
    const int n4 = (NEXP * D_MLP * D_MODEL) / 4;
    const float* src;
    __half* dst;
    if (blockIdx.y == 0)      { src = w1; dst = g_w1h; }
    else if (blockIdx.y == 1) { src = w3; dst = g_w3h; }
    else                      { src = w2; dst = g_w2h; }
    const float4* s4 = reinterpret_cast<const float4*>(src);
    __half2* d2 = reinterpret_cast<__half2*>(dst);
    int i = blockIdx.x * blockDim.x + threadIdx.x;
    for (; i < n4; i += gridDim.x * blockDim.x) {
        float4 v = s4[i];
        d2[2 * i + 0] = __floats2half2_rn(v.x, v.y);
        d2[2 * i + 1] = __floats2half2_rn(v.z, v.w);
    }
}

// ---------------- kernel 1: gating (warp per token) + x->fp16 ----------------
__global__ void gate_kernel(const float* __restrict__ x, const float* __restrict__ wg) {
    int t = blockIdx.x * 4 + (threadIdx.x >> 5);
    int lane = threadIdx.x & 31;
    if (t >= T_TOK) return;
    const float* xr = x + (size_t)t * D_MODEL;
    float acc[NEXP];
#pragma unroll
    for (int e = 0; e < NEXP; e++) acc[e] = 0.f;
    for (int d = lane; d < D_MODEL; d += 32) {
        float xv = xr[d];
        g_xh[(size_t)t * D_MODEL + d] = __float2half_rn(xv);
#pragma unroll
        for (int e = 0; e < NEXP; e++) acc[e] += xv * wg[e * D_MODEL + d];
    }
#pragma unroll
    for (int e = 0; e < NEXP; e++)
#pragma unroll
        for (int o = 16; o; o >>= 1) acc[e] += __shfl_xor_sync(0xFFFFFFFFu, acc[e], o);
    if (lane == 0) {
        int i0 = 0;
        float l0 = acc[0];
#pragma unroll
        for (int e = 1; e < NEXP; e++)
            if (acc[e] > l0) { l0 = acc[e]; i0 = e; }
        int i1 = -1;
        float l1 = -INFINITY;
#pragma unroll
        for (int e = 0; e < NEXP; e++)
            if (e != i0 && acc[e] > l1) { l1 = acc[e]; i1 = e; }
        float e1 = expf(l1 - l0);
        float s = 1.f + e1;
        float w0 = 1.f / s, w1 = e1 / s;
        int p0 = atomicAdd(&g_cnt[i0], 1);
        g_list[i0 * T_TOK + p0] = t;
        g_wts[i0 * T_TOK + p0] = w0;
        int p1 = atomicAdd(&g_cnt[i1], 1);
        g_list[i1 * T_TOK + p1] = t;
        g_wts[i1 * T_TOK + p1] = w1;
    }
}

// ---------------- kernel 2: grouped GEMM1 (X @ W1^T, X @ W3^T) + SwiGLU ----------------
// grid: (D_MLP/BN, T_TOK/BM, NEXP), block: 128
__global__ void __launch_bounds__(128) gemm1_kernel() {
    int e = blockIdx.z, mt = blockIdx.y, nt = blockIdx.x;
    int cnt = g_cnt[e];
    if (mt * BM >= cnt) return;

    __shared__ __align__(16) __half As[BM * PITCH];
    __shared__ __align__(16) __half B1s[BN * PITCH];
    __shared__ __align__(16) __half B3s[BN * PITCH];

    int tid = threadIdx.x;
    int warp = tid >> 5, lane = tid & 31;
    int wm = warp >> 1, wn = warp & 1;
    int g = lane >> 2, tg = lane & 3;

    // global->smem load assignment: 2 threads per row, 16 halves each
    int lr = tid >> 1;       // row 0..63
    int seg = tid & 1;       // segment 0..1
    int s_row = mt * BM + lr;
    int tok = g_list[e * T_TOK + min(s_row, cnt - 1)];
    const uint4* aptr = reinterpret_cast<const uint4*>(g_xh + (size_t)tok * D_MODEL) + seg * 2;
    const uint4* b1ptr = reinterpret_cast<const uint4*>(g_w1h + ((size_t)e * D_MLP + nt * BN + lr) * D_MODEL) + seg * 2;
    const uint4* b3ptr = reinterpret_cast<const uint4*>(g_w3h + ((size_t)e * D_MLP + nt * BN + lr) * D_MODEL) + seg * 2;
    uint4* as4 = reinterpret_cast<uint4*>(&As[lr * PITCH + seg * 16]);
    uint4* b14 = reinterpret_cast<uint4*>(&B1s[lr * PITCH + seg * 16]);
    uint4* b34 = reinterpret_cast<uint4*>(&B3s[lr * PITCH + seg * 16]);

    float c1[2][4][4], c3[2][4][4];
#pragma unroll
    for (int i = 0; i < 2; i++)
#pragma unroll
        for (int j = 0; j < 4; j++)
#pragma unroll
            for (int k = 0; k < 4; k++) { c1[i][j][k] = 0.f; c3[i][j][k] = 0.f; }

    for (int k0 = 0; k0 < D_MODEL; k0 += BK) {
        int ko = k0 >> 3;  // uint4 offset
        uint4 va0 = aptr[ko], va1 = aptr[ko + 1];
        uint4 v10 = b1ptr[ko], v11 = b1ptr[ko + 1];
        uint4 v30 = b3ptr[ko], v31 = b3ptr[ko + 1];
        __syncthreads();
        as4[0] = va0; as4[1] = va1;
        b14[0] = v10; b14[1] = v11;
        b34[0] = v30; b34[1] = v31;
        __syncthreads();
#pragma unroll
        for (int kk = 0; kk < 2; kk++) {
            uint32_t a[2][4], b1r[4][2], b3r[4][2];
#pragma unroll
            for (int tm = 0; tm < 2; tm++) {
                int r0 = wm * 32 + tm * 16 + g;
                a[tm][0] = *reinterpret_cast<const uint32_t*>(&As[(r0) * PITCH + kk * 16 + tg * 2]);
                a[tm][1] = *reinterpret_cast<const uint32_t*>(&As[(r0 + 8) * PITCH + kk * 16 + tg * 2]);
                a[tm][2] = *reinterpret_cast<const uint32_t*>(&As[(r0) * PITCH + kk * 16 + tg * 2 + 8]);
                a[tm][3] = *reinterpret_cast<const uint32_t*>(&As[(r0 + 8) * PITCH + kk * 16 + tg * 2 + 8]);
            }
#pragma unroll
            for (int tn = 0; tn < 4; tn++) {
                int n0 = wn * 32 + tn * 8 + g;
                b1r[tn][0] = *reinterpret_cast<const uint32_t*>(&B1s[n0 * PITCH + kk * 16 + tg * 2]);
                b1r[tn][1] = *reinterpret_cast<const uint32_t*>(&B1s[n0 * PITCH + kk * 16 + tg * 2 + 8]);
                b3r[tn][0] = *reinterpret_cast<const uint32_t*>(&B3s[n0 * PITCH + kk * 16 + tg * 2]);
                b3r[tn][1] = *reinterpret_cast<const uint32_t*>(&B3s[n0 * PITCH + kk * 16 + tg * 2 + 8]);
            }
#pragma unroll
            for (int tm = 0; tm < 2; tm++)
#pragma unroll
                for (int tn = 0; tn < 4; tn++) {
                    mma16816(c1[tm][tn], a[tm], b1r[tn]);
                    mma16816(c3[tm][tn], a[tm], b3r[tn]);
                }
        }
    }

    // epilogue: h = silu(h1) * h3 -> fp16 store
#pragma unroll
    for (int tm = 0; tm < 2; tm++)
#pragma unroll
        for (int pair = 0; pair < 2; pair++) {
            int s = mt * BM + wm * 32 + tm * 16 + g + pair * 8;
            if (s >= cnt) continue;
#pragma unroll
            for (int tn = 0; tn < 4; tn++) {
                float h1a = c1[tm][tn][pair * 2 + 0];
                float h1b = c1[tm][tn][pair * 2 + 1];
                float h3a = c3[tm][tn][pair * 2 + 0];
                float h3b = c3[tm][tn][pair * 2 + 1];
                float ha = h1a / (1.f + expf(-h1a)) * h3a;
                float hb = h1b / (1.f + expf(-h1b)) * h3b;
                int col = nt * BN + wn * 32 + tn * 8 + tg * 2;
                *reinterpret_cast<__half2*>(&g_h[((size_t)e * T_TOK + s) * D_MLP + col]) =
                    __floats2half2_rn(ha, hb);
            }
        }
}

// ---------------- kernel 3: grouped GEMM2 (H @ W2^T) * gate_w, atomic combine ----------------
// grid: (D_MODEL/BN, T_TOK/BM, NEXP), block: 128
__global__ void __launch_bounds__(128) gemm2_kernel(float* __restrict__ out) {
    int e = blockIdx.z, mt = blockIdx.y, nt = blockIdx.x;
    int cnt = g_cnt[e];
    if (mt * BM >= cnt) return;

    __shared__ __align__(16) __half As[BM * PITCH];
    __shared__ __align__(16) __half Bs[BN * PITCH];

    int tid = threadIdx.x;
    int warp = tid >> 5, lane = tid & 31;
    int wm = warp >> 1, wn = warp & 1;
    int g = lane >> 2, tg = lane & 3;

    int lr = tid >> 1;
    int seg = tid & 1;
    const uint4* aptr = reinterpret_cast<const uint4*>(g_h + ((size_t)e * T_TOK + mt * BM + lr) * D_MLP) + seg * 2;
    const uint4* bptr = reinterpret_cast<const uint4*>(g_w2h + ((size_t)e * D_MODEL + nt * BN + lr) * D_MLP) + seg * 2;
    uint4* as4 = reinterpret_cast<uint4*>(&As[lr * PITCH + seg * 16]);
    uint4* bs4 = reinterpret_cast<uint4*>(&Bs[lr * PITCH + seg * 16]);

    float c[2][4][4];
#pragma unroll
    for (int i = 0; i < 2; i++)
#pragma unroll
        for (int j = 0; j < 4; j++)
#pragma unroll
            for (int k = 0; k < 4; k++) c[i][j][k] = 0.f;

    for (int k0 = 0; k0 < D_MLP; k0 += BK) {
        int ko = k0 >> 3;
        uint4 va0 = aptr[ko], va1 = aptr[ko + 1];
        uint4 vb0 = bptr[ko], vb1 = bptr[ko + 1];
        __syncthreads();
        as4[0] = va0; as4[1] = va1;
        bs4[0] = vb0; bs4[1] = vb1;
        __syncthreads();
#pragma unroll
        for (int kk = 0; kk < 2; kk++) {
            uint32_t a[2][4], br[4][2];
#pragma unroll
            for (int tm = 0; tm < 2; tm++) {
                int r0 = wm * 32 + tm * 16 + g;
                a[tm][0] = *reinterpret_cast<const uint32_t*>(&As[(r0) * PITCH + kk * 16 + tg * 2]);
                a[tm][1] = *reinterpret_cast<const uint32_t*>(&As[(r0 + 8) * PITCH + kk * 16 + tg * 2]);
                a[tm][2] = *reinterpret_cast<const uint32_t*>(&As[(r0) * PITCH + kk * 16 + tg * 2 + 8]);
                a[tm][3] = *reinterpret_cast<const uint32_t*>(&As[(r0 + 8) * PITCH + kk * 16 + tg * 2 + 8]);
            }
#pragma unroll
            for (int tn = 0; tn < 4; tn++) {
                int n0 = wn * 32 + tn * 8 + g;
                br[tn][0] = *reinterpret_cast<const uint32_t*>(&Bs[n0 * PITCH + kk * 16 + tg * 2]);
                br[tn][1] = *reinterpret_cast<const uint32_t*>(&Bs[n0 * PITCH + kk * 16 + tg * 2 + 8]);
            }
#pragma unroll
            for (int tm = 0; tm < 2; tm++)
#pragma unroll
                for (int tn = 0; tn < 4; tn++)
                    mma16816(c[tm][tn], a[tm], br[tn]);
        }
    }

    // epilogue: weighted atomic combine into output
#pragma unroll
    for (int tm = 0; tm < 2; tm++)
#pragma unroll
        for (int pair = 0; pair < 2; pair++) {
            int s = mt * BM + wm * 32 + tm * 16 + g + pair * 8;
            if (s >= cnt) continue;
            int token = g_list[e * T_TOK + s];
            float w = g_wts[e * T_TOK + s];
#pragma unroll
            for (int tn = 0; tn < 4; tn++) {
                int col = nt * BN + wn * 32 + tn * 8 + tg * 2;
                float* dst = out + (size_t)token * D_MODEL + col;
                atomicAdd(dst + 0, c[tm][tn][pair * 2 + 0] * w);
                atomicAdd(dst + 1, c[tm][tn][pair * 2 + 1] * w);
            }
        }
}

// ---------------- launch ----------------
extern "C" void kernel_launch(void* const* d_in, const int* in_sizes, int n_in,
                              void* d_out, int out_size) {
    const float* x = (const float*)d_in[0];
    const float* w_gate = (const float*)d_in[1];
    const float* w1 = (const float*)d_in[2];
    const float* w3 = (const float*)d_in[3];
    const float* w2 = (const float*)d_in[4];
    float* out = (float*)d_out;

    // 1. zero output + counters
    zero_kernel<<<1024, 256>>>((float4*)out, (T_TOK * D_MODEL) / 4);

    // 2. weight conversion fp32 -> fp16 (dst selected device-side via blockIdx.y)
    dim3 gcvt(2048, 3);
    cvt_w_kernel<<<gcvt, 256>>>(w1, w3, w2);

    // 3. gating + x conversion
    gate_kernel<<<T_TOK / 4, 128>>>(x, w_gate);

    // 4. grouped GEMM1 + SwiGLU
    dim3 g1(D_MLP / BN, T_TOK / BM, NEXP);
    gemm1_kernel<<<g1, 128>>>();

    // 5. grouped GEMM2 + weighted combine
    dim3 g2(D_MODEL / BN, T_TOK / BM, NEXP);
    gemm2_kernel<<<g2, 128>>>(out);
}

// round 3
// speedup vs baseline: 1.9402x; 1.9402x over previous
#include <cuda_runtime.h>
#include <cuda_fp16.h>
#include <cstdint>
#include <math.h>

// Problem constants
#define T_TOK 4096
#define D_MODEL 1024
#define D_MLP 3584
#define NEXP 8

// GEMM tile config
#define BM 128
#define BN 64
#define BK 64
#define THREADS 256

// smem stage sizes (bytes)
#define A_BYTES (BM * BK * 2)             // 16384
#define B_BYTES (BN * BK * 2)             // 8192
#define STAGE1 (A_BYTES + 2 * B_BYTES)    // 32768 (gemm1: A + B1 + B3)
#define STAGE2 (A_BYTES + B_BYTES)        // 24576 (gemm2: A + B)

// ---------------- device scratch (static: no cudaMalloc allowed) ----------------
static __device__ __align__(16) __half g_xh[T_TOK * D_MODEL];
static __device__ __align__(16) __half g_w1h[NEXP * D_MLP * D_MODEL];
static __device__ __align__(16) __half g_w3h[NEXP * D_MLP * D_MODEL];
static __device__ __align__(16) __half g_w2h[NEXP * D_MODEL * D_MLP];
static __device__ __align__(16) __half g_h[(size_t)NEXP * T_TOK * D_MLP];
static __device__ int    g_cnt[NEXP];
static __device__ int    g_list[NEXP * T_TOK];
static __device__ float  g_wts[NEXP * T_TOK];

// ---------------- helpers ----------------
__device__ __forceinline__ void mma16816(float* c, const uint32_t* a, const uint32_t* b) {
    asm volatile(
        "mma.sync.aligned.m16n8k16.row.col.f32.f16.f16.f32 "
        "{%0,%1,%2,%3}, {%4,%5,%6,%7}, {%8,%9}, {%0,%1,%2,%3};"
        : "+f"(c[0]), "+f"(c[1]), "+f"(c[2]), "+f"(c[3])
        : "r"(a[0]), "r"(a[1]), "r"(a[2]), "r"(a[3]), "r"(b[0]), "r"(b[1]));
}

__device__ __forceinline__ void ldsm4(uint32_t* r, uint32_t saddr) {
    asm volatile("ldmatrix.sync.aligned.m8n8.x4.shared.b16 {%0,%1,%2,%3}, [%4];"
                 : "=r"(r[0]), "=r"(r[1]), "=r"(r[2]), "=r"(r[3]) : "r"(saddr));
}

__device__ __forceinline__ void cp16(uint32_t dst, const void* src) {
    asm volatile("cp.async.cg.shared.global [%0], [%1], 16;" :: "r"(dst), "l"(src));
}
#define CP_COMMIT() asm volatile("cp.async.commit_group;")
#define CP_WAIT1()  asm volatile("cp.async.wait_group 1;")
#define CP_WAIT0()  asm volatile("cp.async.wait_group 0;")

__device__ __forceinline__ uint32_t smem_u32(const void* p) {
    return (uint32_t)__cvta_generic_to_shared(p);
}

// ---------------- kernel 0: zero output + counters ----------------
__global__ void zero_kernel(float4* out4, int n4) {
    int i = blockIdx.x * blockDim.x + threadIdx.x;
    float4 z = make_float4(0.f, 0.f, 0.f, 0.f);
    for (; i < n4; i += gridDim.x * blockDim.x) out4[i] = z;
    if (blockIdx.x == 0 && threadIdx.x < NEXP) g_cnt[threadIdx.x] = 0;
}

// ---------------- weight fp32 -> fp16 (dst selected device-side) ----------------
__global__ void cvt_w_kernel(const float* __restrict__ w1,
                             const float* __restrict__ w3,
                             const float* __restrict__ w2) {
    const int n4 = (NEXP * D_MLP * D_MODEL) / 4;
    const float* src;
    __half* dst;
    if (blockIdx.y == 0)      { src = w1; dst = g_w1h; }
    else if (blockIdx.y == 1) { src = w3; dst = g_w3h; }
    else                      { src = w2; dst = g_w2h; }
    const float4* s4 = reinterpret_cast<const float4*>(src);
    __half2* d2 = reinterpret_cast<__half2*>(dst);
    int i = blockIdx.x * blockDim.x + threadIdx.x;
    for (; i < n4; i += gridDim.x * blockDim.x) {
        float4 v = s4[i];
        d2[2 * i + 0] = __floats2half2_rn(v.x, v.y);
        d2[2 * i + 1] = __floats2half2_rn(v.z, v.w);
    }
}

// ---------------- gating (warp per token) + x->fp16 ----------------
__global__ void gate_kernel(const float* __restrict__ x, const float* __restrict__ wg) {
    int t = blockIdx.x * 4 + (threadIdx.x >> 5);
    int lane = threadIdx.x & 31;
    if (t >= T_TOK) return;
    const float* xr = x + (size_t)t * D_MODEL;
    float acc[NEXP];
#pragma unroll
    for (int e = 0; e < NEXP; e++) acc[e] = 0.f;
    for (int d = lane; d < D_MODEL; d += 32) {
        float xv = xr[d];
        g_xh[(size_t)t * D_MODEL + d] = __float2half_rn(xv);
#pragma unroll
        for (int e = 0; e < NEXP; e++) acc[e] += xv * wg[e * D_MODEL + d];
    }
#pragma unroll
    for (int e = 0; e < NEXP; e++)
#pragma unroll
        for (int o = 16; o; o >>= 1) acc[e] += __shfl_xor_sync(0xFFFFFFFFu, acc[e], o);
    if (lane == 0) {
        int i0 = 0;
        float l0 = acc[0];
#pragma unroll
        for (int e = 1; e < NEXP; e++)
            if (acc[e] > l0) { l0 = acc[e]; i0 = e; }
        int i1 = -1;
        float l1 = -INFINITY;
#pragma unroll
        for (int e = 0; e < NEXP; e++)
            if (e != i0 && acc[e] > l1) { l1 = acc[e]; i1 = e; }
        float e1 = expf(l1 - l0);
        float s = 1.f + e1;
        float w0 = 1.f / s, w1 = e1 / s;
        int p0 = atomicAdd(&g_cnt[i0], 1);
        g_list[i0 * T_TOK + p0] = t;
        g_wts[i0 * T_TOK + p0] = w0;
        int p1 = atomicAdd(&g_cnt[i1], 1);
        g_list[i1 * T_TOK + p1] = t;
        g_wts[i1 * T_TOK + p1] = w1;
    }
}

// ---------------- grouped GEMM1: h = silu(X@W1^T) * (X@W3^T), fp16 out ----------------
// grid: (D_MLP/BN, T_TOK/BM, NEXP), block 256, dynamic smem 2*STAGE1
__global__ void __launch_bounds__(THREADS, 2) gemm1_kernel() {
    int e = blockIdx.z, mt = blockIdx.y, nt = blockIdx.x;
    int cnt = g_cnt[e];
    if (mt * BM >= cnt) return;

    extern __shared__ __align__(128) char sm1[];
    uint32_t sbase = smem_u32(sm1);

    int tid = threadIdx.x, lane = tid & 31, warp = tid >> 5;
    int wm = warp & 3, wn = warp >> 2;       // 4 x 2 warp grid
    int g = lane >> 2, tg = lane & 3;
    int l15 = lane & 15, hi = lane >> 4;

    // ---- global->smem load setup (chunk = 16B = 8 halves; 8 chunks per BK row) ----
    const __half* asrc[4]; uint32_t adst[4];
#pragma unroll
    for (int i = 0; i < 4; i++) {
        int lin = i * THREADS + tid;          // 0..1023 over 128 rows x 8 chunks
        int row = lin >> 3, ch = lin & 7;
        int s = mt * BM + row;
        int tok = g_list[e * T_TOK + min(s, cnt - 1)];
        asrc[i] = g_xh + (size_t)tok * D_MODEL + ch * 8;
        adst[i] = sbase + row * 128 + ((ch ^ (row & 7)) << 4);
    }
    const __half* b1src[2]; const __half* b3src[2]; uint32_t bdst[2];
#pragma unroll
    for (int i = 0; i < 2; i++) {
        int lin = i * THREADS + tid;          // 0..511 over 64 rows x 8 chunks
        int row = lin >> 3, ch = lin & 7;
        size_t off = ((size_t)e * D_MLP + nt * BN + row) * D_MODEL + ch * 8;
        b1src[i] = g_w1h + off;
        b3src[i] = g_w3h + off;
        bdst[i] = sbase + A_BYTES + row * 128 + ((ch ^ (row & 7)) << 4);
    }

    // ---- ldmatrix address precompute ----
    uint32_t aA[2]; int xA[2];
#pragma unroll
    for (int tm = 0; tm < 2; tm++) {
        int r = wm * 32 + tm * 16 + l15;
        aA[tm] = sbase + r * 128;
        xA[tm] = r & 7;
    }
    uint32_t aB[2]; int xB[2];
#pragma unroll
    for (int ns = 0; ns < 2; ns++) {
        int r = wn * 32 + ns * 16 + l15;
        aB[ns] = sbase + A_BYTES + r * 128;
        xB[ns] = r & 7;
    }

    float c1[2][4][4] = {}, c3[2][4][4] = {};

    const int NK = D_MODEL / BK;  // 16

    // prologue: stage 0
#pragma unroll
    for (int i = 0; i < 4; i++) cp16(adst[i], asrc[i]);
#pragma unroll
    for (int i = 0; i < 2; i++) { cp16(bdst[i], b1src[i]); cp16(bdst[i] + B_BYTES, b3src[i]); }
    CP_COMMIT();

    for (int kt = 0; kt < NK; kt++) {
        uint32_t so = (uint32_t)(kt & 1) * STAGE1;
        if (kt + 1 < NK) {
            uint32_t sn = (uint32_t)((kt + 1) & 1) * STAGE1;
            int koff = (kt + 1) * BK;
#pragma unroll
            for (int i = 0; i < 4; i++) cp16(adst[i] + sn, asrc[i] + koff);
#pragma unroll
            for (int i = 0; i < 2; i++) {
                cp16(bdst[i] + sn, b1src[i] + koff);
                cp16(bdst[i] + sn + B_BYTES, b3src[i] + koff);
            }
            CP_COMMIT();
            CP_WAIT1();
        } else {
            CP_WAIT0();
        }
        __syncthreads();
#pragma unroll
        for (int kk = 0; kk < 4; kk++) {
            uint32_t a[2][4], q1[2][4], q3[2][4];
#pragma unroll
            for (int tm = 0; tm < 2; tm++)
                ldsm4(a[tm], aA[tm] + so + ((uint32_t)((kk * 2 + hi) ^ xA[tm]) << 4));
#pragma unroll
            for (int ns = 0; ns < 2; ns++) {
                uint32_t sw = (uint32_t)((kk * 2 + hi) ^ xB[ns]) << 4;
                ldsm4(q1[ns], aB[ns] + so + sw);
                ldsm4(q3[ns], aB[ns] + so + sw + B_BYTES);
            }
#pragma unroll
            for (int tm = 0; tm < 2; tm++)
#pragma unroll
                for (int ns = 0; ns < 2; ns++) {
                    uint32_t b1a[2] = {q1[ns][0], q1[ns][2]}, b1b[2] = {q1[ns][1], q1[ns][3]};
                    uint32_t b3a[2] = {q3[ns][0], q3[ns][2]}, b3b[2] = {q3[ns][1], q3[ns][3]};
                    mma16816(c1[tm][ns * 2 + 0], a[tm], b1a);
                    mma16816(c1[tm][ns * 2 + 1], a[tm], b1b);
                    mma16816(c3[tm][ns * 2 + 0], a[tm], b3a);
                    mma16816(c3[tm][ns * 2 + 1], a[tm], b3b);
                }
        }
        __syncthreads();
    }

    // epilogue: h = silu(h1) * h3 -> fp16
#pragma unroll
    for (int tm = 0; tm < 2; tm++)
#pragma unroll
        for (int pair = 0; pair < 2; pair++) {
            int s = mt * BM + wm * 32 + tm * 16 + g + pair * 8;
            if (s >= cnt) continue;
#pragma unroll
            for (int tn = 0; tn < 4; tn++) {
                float h1a = c1[tm][tn][pair * 2 + 0];
                float h1b = c1[tm][tn][pair * 2 + 1];
                float h3a = c3[tm][tn][pair * 2 + 0];
                float h3b = c3[tm][tn][pair * 2 + 1];
                float ha = h1a / (1.f + expf(-h1a)) * h3a;
                float hb = h1b / (1.f + expf(-h1b)) * h3b;
                int col = nt * BN + wn * 32 + tn * 8 + tg * 2;
                *reinterpret_cast<__half2*>(&g_h[((size_t)e * T_TOK + s) * D_MLP + col]) =
                    __floats2half2_rn(ha, hb);
            }
        }
}

// ---------------- grouped GEMM2: out += w * (H @ W2^T) ----------------
// grid: (D_MODEL/BN, T_TOK/BM, NEXP), block 256, dynamic smem 2*STAGE2
__global__ void __launch_bounds__(THREADS, 2) gemm2_kernel(float* __restrict__ out) {
    int e = blockIdx.z, mt = blockIdx.y, nt = blockIdx.x;
    int cnt = g_cnt[e];
    if (mt * BM >= cnt) return;

    extern __shared__ __align__(128) char sm2[];
    uint32_t sbase = smem_u32(sm2);

    int tid = threadIdx.x, lane = tid & 31, warp = tid >> 5;
    int wm = warp & 3, wn = warp >> 2;
    int g = lane >> 2, tg = lane & 3;
    int l15 = lane & 15, hi = lane >> 4;

    const __half* asrc[4]; uint32_t adst[4];
#pragma unroll
    for (int i = 0; i < 4; i++) {
        int lin = i * THREADS + tid;
        int row = lin >> 3, ch = lin & 7;
        asrc[i] = g_h + ((size_t)e * T_TOK + mt * BM + row) * D_MLP + ch * 8;
        adst[i] = sbase + row * 128 + ((ch ^ (row & 7)) << 4);
    }
    const __half* bsrc[2]; uint32_t bdst[2];
#pragma unroll
    for (int i = 0; i < 2; i++) {
        int lin = i * THREADS + tid;
        int row = lin >> 3, ch = lin & 7;
        bsrc[i] = g_w2h + ((size_t)e * D_MODEL + nt * BN + row) * D_MLP + ch * 8;
        bdst[i] = sbase + A_BYTES + row * 128 + ((ch ^ (row & 7)) << 4);
    }

    uint32_t aA[2]; int xA[2];
#pragma unroll
    for (int tm = 0; tm < 2; tm++) {
        int r = wm * 32 + tm * 16 + l15;
        aA[tm] = sbase + r * 128;
        xA[tm] = r & 7;
    }
    uint32_t aB[2]; int xB[2];
#pragma unroll
    for (int ns = 0; ns < 2; ns++) {
        int r = wn * 32 + ns * 16 + l15;
        aB[ns] = sbase + A_BYTES + r * 128;
        xB[ns] = r & 7;
    }

    float c[2][4][4] = {};

    const int NK = D_MLP / BK;  // 56

#pragma unroll
    for (int i = 0; i < 4; i++) cp16(adst[i], asrc[i]);
#pragma unroll
    for (int i = 0; i < 2; i++) cp16(bdst[i], bsrc[i]);
    CP_COMMIT();

    for (int kt = 0; kt < NK; kt++) {
        uint32_t so = (uint32_t)(kt & 1) * STAGE2;
        if (kt + 1 < NK) {
            uint32_t sn = (uint32_t)((kt + 1) & 1) * STAGE2;
            int koff = (kt + 1) * BK;
#pragma unroll
            for (int i = 0; i < 4; i++) cp16(adst[i] + sn, asrc[i] + koff);
#pragma unroll
            for (int i = 0; i < 2; i++) cp16(bdst[i] + sn, bsrc[i] + koff);
            CP_COMMIT();
            CP_WAIT1();
        } else {
            CP_WAIT0();
        }
        __syncthreads();
#pragma unroll
        for (int kk = 0; kk < 4; kk++) {
            uint32_t a[2][4], q[2][4];
#pragma unroll
            for (int tm = 0; tm < 2; tm++)
                ldsm4(a[tm], aA[tm] + so + ((uint32_t)((kk * 2 + hi) ^ xA[tm]) << 4));
#pragma unroll
            for (int ns = 0; ns < 2; ns++)
                ldsm4(q[ns], aB[ns] + so + ((uint32_t)((kk * 2 + hi) ^ xB[ns]) << 4));
#pragma unroll
            for (int tm = 0; tm < 2; tm++)
#pragma unroll
                for (int ns = 0; ns < 2; ns++) {
                    uint32_t ba[2] = {q[ns][0], q[ns][2]}, bb[2] = {q[ns][1], q[ns][3]};
                    mma16816(c[tm][ns * 2 + 0], a[tm], ba);
                    mma16816(c[tm][ns * 2 + 1], a[tm], bb);
                }
        }
        __syncthreads();
    }

    // epilogue: weighted atomic combine
#pragma unroll
    for (int tm = 0; tm < 2; tm++)
#pragma unroll
        for (int pair = 0; pair < 2; pair++) {
            int s = mt * BM + wm * 32 + tm * 16 + g + pair * 8;
            if (s >= cnt) continue;
            int token = g_list[e * T_TOK + s];
            float w = g_wts[e * T_TOK + s];
#pragma unroll
            for (int tn = 0; tn < 4; tn++) {
                int col = nt * BN + wn * 32 + tn * 8 + tg * 2;
                float* dst = out + (size_t)token * D_MODEL + col;
                atomicAdd(dst + 0, c[tm][tn][pair * 2 + 0] * w);
                atomicAdd(dst + 1, c[tm][tn][pair * 2 + 1] * w);
            }
        }
}

// ---------------- launch ----------------
extern "C" void kernel_launch(void* const* d_in, const int* in_sizes, int n_in,
                              void* d_out, int out_size) {
    const float* x = (const float*)d_in[0];
    const float* w_gate = (const float*)d_in[1];
    const float* w1 = (const float*)d_in[2];
    const float* w3 = (const float*)d_in[3];
    const float* w2 = (const float*)d_in[4];
    float* out = (float*)d_out;

    cudaFuncSetAttribute(gemm1_kernel, cudaFuncAttributeMaxDynamicSharedMemorySize, 2 * STAGE1);
    cudaFuncSetAttribute(gemm2_kernel, cudaFuncAttributeMaxDynamicSharedMemorySize, 2 * STAGE2);

    // 1. zero output + counters
    zero_kernel<<<1024, 256>>>((float4*)out, (T_TOK * D_MODEL) / 4);

    // 2. weight conversion fp32 -> fp16
    dim3 gcvt(2048, 3);
    cvt_w_kernel<<<gcvt, 256>>>(w1, w3, w2);

    // 3. gating + x conversion
    gate_kernel<<<T_TOK / 4, 128>>>(x, w_gate);

    // 4. grouped GEMM1 + SwiGLU
    dim3 g1(D_MLP / BN, T_TOK / BM, NEXP);
    gemm1_kernel<<<g1, THREADS, 2 * STAGE1>>>();

    // 5. grouped GEMM2 + weighted combine
    dim3 g2(D_MODEL / BN, T_TOK / BM, NEXP);
    gemm2_kernel<<<g2, THREADS, 2 * STAGE2>>>(out);
}